// round 15
// baseline (speedup 1.0000x reference)
#include <cuda_runtime.h>
#include <math.h>

// Problem constants
#define MM    96      // MMAX
#define LLM   96      // LMAX
#define TLAT  255     // NLAT = 4*64-1
#define BC    256     // B*C = 4*64
#define NPIX  49152   // 12 * 64^2

typedef unsigned long long ull;

// ---- f32x2 packed math helpers ---------------------------------------------
__device__ __forceinline__ ull pack2(float lo, float hi) {
    ull r; asm("mov.b64 %0, {%1, %2};" : "=l"(r) : "f"(lo), "f"(hi)); return r;
}
__device__ __forceinline__ void unpack2(ull v, float& lo, float& hi) {
    asm("mov.b64 {%0, %1}, %2;" : "=f"(lo), "=f"(hi) : "l"(v));
}
__device__ __forceinline__ ull fma2(ull a, ull b, ull c) {
    ull d; asm("fma.rn.f32x2 %0, %1, %2, %3;" : "=l"(d) : "l"(a), "l"(b), "l"(c)); return d;
}

// Scratch: phase-rotated spectral coefficients, pre-scaled by 2 (irfft weight).
// Layout [bc][m][t].
__device__ float g_re[BC * MM * TLAT];
__device__ float g_im[BC * MM * TLAT];

// ---------------------------------------------------------------------------
// Kernel A with latitude mirror symmetry (exact R9 version, best known):
//   P_lm(-z) = (-1)^(l+m) P_lm(z);  ring t and 254-t have z -> -z.
//   ring k = E+O, ring 254-k = (-1)^m (E-O).
// Thread: 2 ring-pairs (rp, rp+64) x 4 bc.
// Grid: (m=96, bcChunk=32), Block: 128 threads.
// ---------------------------------------------------------------------------
__global__ __launch_bounds__(128)
void legendre_phase_kernel(const float* __restrict__ xr,
                           const float* __restrict__ xi,
                           const float* __restrict__ pct,
                           const float* __restrict__ off)
{
    const int m     = blockIdx.x;
    const int bc0   = blockIdx.y * 8;
    const int tid   = threadIdx.x;
    const int bcsub = (tid & 1) * 4;
    const int rp    = tid >> 1;
    const int kA    = rp;
    const int kB    = rp + 64;

    __shared__ __align__(16) float2 sx[LLM * 8];

    for (int idx = tid; idx < LLM * 8; idx += 128) {
        const int l = idx >> 3;
        const int b = idx & 7;
        const int g = ((bc0 + b) * LLM + l) * MM + m;
        sx[idx] = make_float2(xr[g], xi[g]);
    }
    __syncthreads();

    ull EA[4], OA[4], EB[4], OB[4];
    #pragma unroll
    for (int b = 0; b < 4; ++b) { EA[b]=0ull; OA[b]=0ull; EB[b]=0ull; OB[b]=0ull; }

    const float* __restrict__ pm = pct + (size_t)m * LLM * TLAT;

    #pragma unroll 2
    for (int l = 0; l < LLM; l += 2) {
        {
            const float pa = pm[(size_t)l * TLAT + kA];
            const float pb = pm[(size_t)l * TLAT + kB];
            const ulonglong2 v0 = *(const ulonglong2*)(sx + l * 8 + bcsub);
            const ulonglong2 v1 = *(const ulonglong2*)(sx + l * 8 + bcsub + 2);
            const ull ppa = pack2(pa, pa), ppb = pack2(pb, pb);
            EA[0]=fma2(v0.x,ppa,EA[0]); EA[1]=fma2(v0.y,ppa,EA[1]);
            EA[2]=fma2(v1.x,ppa,EA[2]); EA[3]=fma2(v1.y,ppa,EA[3]);
            EB[0]=fma2(v0.x,ppb,EB[0]); EB[1]=fma2(v0.y,ppb,EB[1]);
            EB[2]=fma2(v1.x,ppb,EB[2]); EB[3]=fma2(v1.y,ppb,EB[3]);
        }
        {
            const int lo = l + 1;
            const float pa = pm[(size_t)lo * TLAT + kA];
            const float pb = pm[(size_t)lo * TLAT + kB];
            const ulonglong2 v0 = *(const ulonglong2*)(sx + lo * 8 + bcsub);
            const ulonglong2 v1 = *(const ulonglong2*)(sx + lo * 8 + bcsub + 2);
            const ull ppa = pack2(pa, pa), ppb = pack2(pb, pb);
            OA[0]=fma2(v0.x,ppa,OA[0]); OA[1]=fma2(v0.y,ppa,OA[1]);
            OA[2]=fma2(v1.x,ppa,OA[2]); OA[3]=fma2(v1.y,ppa,OA[3]);
            OB[0]=fma2(v0.x,ppb,OB[0]); OB[1]=fma2(v0.y,ppb,OB[1]);
            OB[2]=fma2(v1.x,ppb,OB[2]); OB[3]=fma2(v1.y,ppb,OB[3]);
        }
    }

    const float msign = (m & 1) ? -1.0f : 1.0f;

    #define EMIT_PAIR(KK, EACC, OACC, SELF)                                  \
    {                                                                        \
        const int kk = (KK);                                                 \
        const int km = 254 - kk;                                             \
        float s1, c1s, s2, c2s;                                              \
        sincosf(off[kk * MM + m], &s1, &c1s);                                \
        sincosf(off[km * MM + m], &s2, &c2s);                                \
        _Pragma("unroll")                                                    \
        for (int b = 0; b < 4; ++b) {                                        \
            float er, ei, orr, oii;                                          \
            unpack2(EACC[b], er, ei);                                        \
            unpack2(OACC[b], orr, oii);                                      \
            const int bc = bc0 + bcsub + b;                                  \
            const size_t o1 = ((size_t)bc * MM + m) * TLAT + kk;             \
            const float r1 = er + orr, i1 = ei + oii;                        \
            g_re[o1] = 2.0f * (r1 * c1s - i1 * s1);                          \
            g_im[o1] = 2.0f * (r1 * s1 + i1 * c1s);                          \
            if (!(SELF)) {                                                   \
                const float r2 = msign * (er - orr), i2 = msign * (ei - oii);\
                const size_t o2 = ((size_t)bc * MM + m) * TLAT + km;         \
                g_re[o2] = 2.0f * (r2 * c2s - i2 * s2);                      \
                g_im[o2] = 2.0f * (r2 * s2 + i2 * c2s);                      \
            }                                                                \
        }                                                                    \
    }

    EMIT_PAIR(kA, EA, OA, false)
    EMIT_PAIR(kB, EB, OB, (kB == 127))
    #undef EMIT_PAIR
}

// ---------------------------------------------------------------------------
// Kernel B: per-ring inverse real DFT (norm='forward', n % 4 == 0).
// Quarter-wave split + j-pairing; TWO bc per thread (light registers).
// Block = 64 threads = 2 warps; warp w handles bc pair w of the staged 4-bc
// tile.  Thread handles j0=2*(tid&31), j1=j0+1.
// Grid: (bcChunk=64, t=255), Block: 64 threads.
// ---------------------------------------------------------------------------
__global__ __launch_bounds__(64)
void ring_idft_kernel(float* __restrict__ out)
{
    const int t    = blockIdx.y;
    const int bc0  = blockIdx.x * 4;
    const int tid  = threadIdx.x;
    const int wsel = tid >> 5;          // 0 -> bc01, 1 -> bc23
    const int lane = tid & 31;

    int n, roff;
    if (t <= 62)       { n = 4 * (t + 1); roff = 2 * t * (t + 1); }
    else if (t <= 191) { n = 256;         roff = 8064 + 256 * (t - 63); }
    else               { const int w = 255 - t; n = 4 * w; roff = NPIX - 2 * w * (w + 1); }

    const int nh   = n >> 1;
    const int n4   = n >> 2;
    const int kend = (nh - 1 < MM - 1) ? (nh - 1) : (MM - 1);
    const int kmax = (nh < MM - 1) ? nh : (MM - 1);

    __shared__ __align__(16) float sr4[MM * 4];
    __shared__ __align__(16) float si4[MM * 4];

    for (int idx = tid; idx < (kmax + 1) * 4; idx += 64) {
        const int mm = idx >> 2;
        const int b  = idx & 3;
        const size_t g = ((size_t)(bc0 + b) * MM + mm) * TLAT + t;
        sr4[idx] = g_re[g];
        si4[idx] = g_im[g];
    }
    __syncthreads();

    const int j0 = 2 * lane;
    if (j0 >= n4) return;
    const int j1 = j0 + 1;
    const bool a1 = (j1 < n4);

    // Accumulators: [chain 0/1][residue] single packed pair (2 bc).
    ull U0_0, U1_0, U2_0, U3_0, V1_0, V3_0;
    ull U0_1, U1_1, U2_1, U3_1, V1_1, V3_1;

    {   // bin 0 -> U0 (0.5 * re)
        const ull rp = *(const ull*)(sr4 + 2 * wsel);
        const ull half = pack2(0.5f, 0.5f);
        U0_0 = fma2(rp, half, 0ull);
        U0_1 = U0_0;
    }
    U1_0=U2_0=U3_0=V1_0=V3_0=0ull;
    U1_1=U2_1=U3_1=V1_1=V3_1=0ull;

    const float tstep = 6.283185307179586f / (float)n;
    float stc0, sts0, stc1, sts1;
    sincosf(tstep * (float)j0, &sts0, &stc0);
    sincosf(tstep * (float)j1, &sts1, &stc1);
    float ca = stc0, sa = sts0;   // chain j0
    float cb = stc1, sb = sts1;   // chain j1

    #define LOADK(K)                                                        \
        const ull rp = *(const ull*)(sr4 + (K) * 4 + 2 * wsel);             \
        const ull ip = *(const ull*)(si4 + (K) * 4 + 2 * wsel);

    // U += re*c - im*s (both chains)
    #define ACC_U2(K, A0, A1)                                               \
    {                                                                       \
        LOADK(K)                                                            \
        {                                                                   \
            const ull cc = pack2(ca, ca), ns = pack2(-sa, -sa);             \
            A0 = fma2(rp, cc, A0); A0 = fma2(ip, ns, A0);                   \
        }                                                                   \
        {                                                                   \
            const ull cc = pack2(cb, cb), ns = pack2(-sb, -sb);             \
            A1 = fma2(rp, cc, A1); A1 = fma2(ip, ns, A1);                   \
        }                                                                   \
    }
    // U += re*c - im*s ; V += re*s + im*c (both chains)
    #define ACC_UV2(K, A0, VA0, A1, VA1)                                    \
    {                                                                       \
        LOADK(K)                                                            \
        {                                                                   \
            const ull cc = pack2(ca, ca), ns = pack2(-sa, -sa), ss = pack2(sa, sa); \
            A0  = fma2(rp, cc, A0);  A0  = fma2(ip, ns, A0);                \
            VA0 = fma2(rp, ss, VA0); VA0 = fma2(ip, cc, VA0);               \
        }                                                                   \
        {                                                                   \
            const ull cc = pack2(cb, cb), ns = pack2(-sb, -sb), ss = pack2(sb, sb); \
            A1  = fma2(rp, cc, A1);  A1  = fma2(ip, ns, A1);                \
            VA1 = fma2(rp, ss, VA1); VA1 = fma2(ip, cc, VA1);               \
        }                                                                   \
    }
    #define ROT2()                                                          \
    {                                                                       \
        const float na = fmaf(ca, stc0, -sa * sts0);                        \
        const float ma = fmaf(sa, stc0,  ca * sts0);                        \
        ca = na; sa = ma;                                                   \
        const float nb = fmaf(cb, stc1, -sb * sts1);                        \
        const float mb = fmaf(sb, stc1,  cb * sts1);                        \
        cb = nb; sb = mb;                                                   \
    }

    int k = 1;
    for (; k + 3 <= kend; k += 4) {
        ACC_UV2(k,     U1_0,V1_0, U1_1,V1_1) ROT2()
        ACC_U2 (k + 1, U2_0, U2_1)           ROT2()
        ACC_UV2(k + 2, U3_0,V3_0, U3_1,V3_1) ROT2()
        ACC_U2 (k + 3, U0_0, U0_1)           ROT2()
    }
    for (; k <= kend; ++k) {
        const int r = k & 3;
        if (r == 1)      { ACC_UV2(k, U1_0,V1_0, U1_1,V1_1) }
        else if (r == 2) { ACC_U2 (k, U2_0, U2_1) }
        else if (r == 3) { ACC_UV2(k, U3_0,V3_0, U3_1,V3_1) }
        else             { ACC_U2 (k, U0_0, U0_1) }
        ROT2()
    }
    #undef LOADK
    #undef ACC_U2
    #undef ACC_UV2
    #undef ROT2

    float w[2] = {0.f, 0.f};
    if (nh < MM) {
        w[0] = 0.5f * sr4[nh * 4 + 2 * wsel + 0];
        w[1] = 0.5f * sr4[nh * 4 + 2 * wsel + 1];
    }

    float u0[2][2], u1[2][2], u2[2][2], u3[2][2], v1[2][2], v3[2][2];
    unpack2(U0_0, u0[0][0], u0[0][1]);
    unpack2(U1_0, u1[0][0], u1[0][1]);
    unpack2(U2_0, u2[0][0], u2[0][1]);
    unpack2(U3_0, u3[0][0], u3[0][1]);
    unpack2(V1_0, v1[0][0], v1[0][1]);
    unpack2(V3_0, v3[0][0], v3[0][1]);
    unpack2(U0_1, u0[1][0], u0[1][1]);
    unpack2(U1_1, u1[1][0], u1[1][1]);
    unpack2(U2_1, u2[1][0], u2[1][1]);
    unpack2(U3_1, u3[1][0], u3[1][1]);
    unpack2(V1_1, v1[1][0], v1[1][1]);
    unpack2(V3_1, v3[1][0], v3[1][1]);

    float y[2][4][2];
    #pragma unroll
    for (int jj = 0; jj < 2; ++jj) {
        #pragma unroll
        for (int b = 0; b < 2; ++b) {
            const float P  = u0[jj][b] + u2[jj][b];
            const float Md = u0[jj][b] - u2[jj][b];
            const float Cc = u1[jj][b] + u3[jj][b];
            const float Dd = v1[jj][b] - v3[jj][b];
            y[jj][0][b] = P + Cc;
            y[jj][1][b] = Md - Dd;
            y[jj][2][b] = P - Cc;
            y[jj][3][b] = Md + Dd;
        }
    }

    const size_t obase = (size_t)(bc0 + 2 * wsel) * NPIX + roff;
    if ((n4 & 1) == 0) {
        // n4 even: j0 even (+w), j1 odd (-w); paired float2 stores.
        #pragma unroll
        for (int q = 0; q < 4; ++q) {
            #pragma unroll
            for (int b = 0; b < 2; ++b) {
                const float2 val = make_float2(y[0][q][b] + w[b],
                                               y[1][q][b] - w[b]);
                *(float2*)(out + obase + (size_t)b * NPIX + q * n4 + j0) = val;
            }
        }
    } else {
        #pragma unroll
        for (int q = 0; q < 4; ++q) {
            const int p0 = j0 + q * n4;
            const float sg0 = (p0 & 1) ? -1.0f : 1.0f;
            #pragma unroll
            for (int b = 0; b < 2; ++b)
                out[obase + (size_t)b * NPIX + p0] = fmaf(sg0, w[b], y[0][q][b]);
            if (a1) {
                const float sg1 = -sg0;
                #pragma unroll
                for (int b = 0; b < 2; ++b)
                    out[obase + (size_t)b * NPIX + p0 + 1] = fmaf(sg1, w[b], y[1][q][b]);
            }
        }
    }
}

// ---------------------------------------------------------------------------
extern "C" void kernel_launch(void* const* d_in, const int* in_sizes, int n_in,
                              void* d_out, int out_size)
{
    const float* xr  = (const float*)d_in[0];  // (4,64,96,96)
    const float* xi  = (const float*)d_in[1];  // (4,64,96,96)
    const float* pct = (const float*)d_in[2];  // (96,96,255)
    const float* off = (const float*)d_in[3];  // (255,96)
    float* out = (float*)d_out;                // (4,64,49152)

    {
        dim3 grid(MM, BC / 8);     // 96 x 32
        legendre_phase_kernel<<<grid, 128>>>(xr, xi, pct, off);
    }
    {
        dim3 grid(BC / 4, TLAT);   // 64 x 255
        ring_idft_kernel<<<grid, 64>>>(out);
    }
}